// round 16
// baseline (speedup 1.0000x reference)
#include <cuda_runtime.h>
#include <cuda_bf16.h>
#include <cstdint>

// ======================= problem constants =======================
#define NB   3
#define BSZ  256
#define NF   8192
#define DDIM 2048
#define TEMP_INV 20.0f
#define NEPS 1e-12f

// GEMM tiling (R9 config)
#define BM 256
#define BN 64
#define BK 64
#define NK (DDIM / BK)                 // 32
#define A_STAGE_BYTES (BM * BK * 2)    // 32768
#define B_STAGE_BYTES (BN * BK * 2)    // 8192
#define SMEM_DYN (3 * A_STAGE_BYTES + 2 * B_STAGE_BYTES)  // 114688

// tile schedule: 384 tiles; first 296 full-K, last 88 (br=2, ntile>=40) split 3-way.
#define NT_FULL 296
#define SPLIT_NT0 40
#define EXCOLS ((128 - SPLIT_NT0) * BN)  // 5632
#define EXCOL0 (SPLIT_NT0 * BN)          // 2560

// ======================= static device scratch =======================
__device__ __align__(256) __nv_bfloat16 g_xn[NB * BSZ * DDIM];
__device__ float g_x2[NB * BSZ];
__device__ float g_f2[NB * NF];
__device__ __align__(256) __nv_bfloat16 g_dotb[(size_t)NB * BSZ * NF];   // dots in bf16
__device__ __align__(256) float g_ex[(size_t)2 * BSZ * EXCOLS];          // split-K partials fp32
__device__ float g_f2x[2 * EXCOLS];
__device__ float g_rowloss[NB * BSZ];
__device__ int g_count;

// ======================= helpers =======================
__device__ __forceinline__ uint32_t smem_u32(const void* p) {
    uint32_t a;
    asm("{ .reg .u64 t; cvta.to.shared.u64 t, %1; cvt.u32.u64 %0, t; }" : "=r"(a) : "l"(p));
    return a;
}

__device__ __forceinline__ void cp16(uint32_t saddr, const void* g) {
    asm volatile("cp.async.cg.shared.global [%0], [%1], 16;" :: "r"(saddr), "l"(g) : "memory");
}
#define CP_COMMIT() asm volatile("cp.async.commit_group;" ::: "memory")
#define CP_WAIT0()  asm volatile("cp.async.wait_group 0;" ::: "memory")
#define CP_WAIT1()  asm volatile("cp.async.wait_group 1;" ::: "memory")

__device__ __forceinline__ void ldsm_x4(uint32_t* r, uint32_t addr) {
    asm volatile("ldmatrix.sync.aligned.m8n8.x4.shared.b16 {%0,%1,%2,%3}, [%4];"
                 : "=r"(r[0]), "=r"(r[1]), "=r"(r[2]), "=r"(r[3]) : "r"(addr));
}

__device__ __forceinline__ void mma16816(float* c, const uint32_t* a, uint32_t b0, uint32_t b1) {
    asm volatile(
        "mma.sync.aligned.m16n8k16.row.col.f32.bf16.bf16.f32 "
        "{%0,%1,%2,%3}, {%4,%5,%6,%7}, {%8,%9}, {%0,%1,%2,%3};"
        : "+f"(c[0]), "+f"(c[1]), "+f"(c[2]), "+f"(c[3])
        : "r"(a[0]), "r"(a[1]), "r"(a[2]), "r"(a[3]), "r"(b0), "r"(b1));
}

__device__ __forceinline__ void sts128u(uint32_t addr, uint32_t x, uint32_t y, uint32_t z, uint32_t w) {
    asm volatile("st.shared.v4.b32 [%0], {%1, %2, %3, %4};"
                 :: "r"(addr), "r"(x), "r"(y), "r"(z), "r"(w) : "memory");
}

__device__ __forceinline__ float blockReduceSum(float v) {
    __shared__ float red[8];
    const unsigned m = 0xffffffffu;
    v += __shfl_xor_sync(m, v, 16);
    v += __shfl_xor_sync(m, v, 8);
    v += __shfl_xor_sync(m, v, 4);
    v += __shfl_xor_sync(m, v, 2);
    v += __shfl_xor_sync(m, v, 1);
    __syncthreads();
    if ((threadIdx.x & 31) == 0) red[threadIdx.x >> 5] = v;
    __syncthreads();
    if (threadIdx.x < 8) {
        v = red[threadIdx.x];
        v += __shfl_xor_sync(0xffu, v, 4);
        v += __shfl_xor_sync(0xffu, v, 2);
        v += __shfl_xor_sync(0xffu, v, 1);
    }
    return v;
}

// ======================= kernel 1: normalize x rows -> bf16 (2 rows/block) ===========
__global__ void __launch_bounds__(256) prep_x_kernel(
    const float* __restrict__ x0, const float* __restrict__ x1, const float* __restrict__ x2)
{
    const int tid = threadIdx.x;
#pragma unroll
    for (int half = 0; half < 2; half++) {
        const int r = blockIdx.x * 2 + half;
        const int br = r >> 8;
        const int b = r & 255;
        const float* base = (br == 0) ? x0 : (br == 1) ? x1 : x2;
        const float4* src = (const float4*)(base + (size_t)b * DDIM);
        __nv_bfloat162* dst = (__nv_bfloat162*)(g_xn + (size_t)r * DDIM);

        float4 v[2];
        float ss = 0.0f;
#pragma unroll
        for (int i = 0; i < 2; i++) {
            v[i] = src[tid + i * 256];
            ss += v[i].x * v[i].x + v[i].y * v[i].y + v[i].z * v[i].z + v[i].w * v[i].w;
        }
        ss = blockReduceSum(ss);
        __shared__ float s_bcast;
        if (tid == 0) s_bcast = ss;
        __syncthreads();
        ss = s_bcast;

        float nrm = sqrtf(ss);
        float scale = 1.0f / fmaxf(nrm, NEPS);
        if (tid == 0) g_x2[r] = ss * scale * scale;
#pragma unroll
        for (int i = 0; i < 2; i++) {
            dst[(tid + i * 256) * 2 + 0] = __floats2bfloat162_rn(v[i].x * scale, v[i].y * scale);
            dst[(tid + i * 256) * 2 + 1] = __floats2bfloat162_rn(v[i].z * scale, v[i].w * scale);
        }
        __syncthreads();
    }
}

// ======================= kernel 2: fused convert + GEMM + f2, asymmetric split-K ====
__global__ void __launch_bounds__(256, 2) gemm_fused_kernel(
    const float* __restrict__ f0, const float* __restrict__ f1, const float* __restrict__ f2in)
{
    extern __shared__ __align__(128) char dyn[];
    const uint32_t sAu  = smem_u32(dyn);                         // 3 x 32KB
    const uint32_t sBcu = sAu + 3 * A_STAGE_BYTES;               // 2 x 8KB

    const int tid = threadIdx.x;
    const int wid = tid >> 5;
    const int lid = tid & 31;

    // ---- tile decode ----
    const int bid = blockIdx.x;
    int br, ntile, part, kbeg, nk;
    if (bid < NT_FULL) {
        br = bid >> 7; ntile = bid & 127; part = 0; kbeg = 0; nk = NK;
    } else {
        int u = bid - NT_FULL;
        int st = u / 3;
        part = u - st * 3;
        br = 2; ntile = SPLIT_NT0 + st;
        kbeg = (part == 0) ? 0 : ((part == 1) ? 11 : 22);
        nk = (part == 0) ? 11 : ((part == 1) ? 11 : 10);
    }
    const int n0 = ntile * BN;
    const int warp_m = wid & 3;
    const int warp_n = wid >> 2;

    const __nv_bfloat16* __restrict__ Ab = g_xn + (size_t)(br * BSZ) * DDIM;
    const float* __restrict__ Fb = ((br == 0) ? f0 : (br == 1) ? f1 : f2in) + (size_t)n0 * DDIM;

    // --- A cp.async mapping ---
    const int arow = tid >> 3;
    const int aseg = tid & 7;
    const uint32_t soA = (uint32_t)(arow * 128 + ((aseg ^ (arow & 7)) << 4));
    const __nv_bfloat16* gA = Ab + (size_t)arow * DDIM + aseg * 8;

    // --- B mapping ---
    const int brow = tid >> 3;
    const int bseg = tid & 7;
    const float* gB0 = Fb + (size_t)brow * DDIM + bseg * 8;
    const float* gB1 = gB0 + (size_t)32 * DDIM;
    const uint32_t dstB = (uint32_t)(brow * 128 + ((bseg ^ (brow & 7)) << 4));

    // --- ldmatrix fragment bases ---
    const int rowA = warp_m * 64 + (lid & 15);
    const uint32_t xA = (uint32_t)(rowA & 7);
    const int rowB0 = warp_n * 32 + (lid & 15);
    const int rowB1 = rowB0 + 16;
    const uint32_t xB0 = (uint32_t)(rowB0 & 7);
    const uint32_t xB1 = (uint32_t)(rowB1 & 7);
    const uint32_t hi = (uint32_t)(lid >> 4);

    float acc[4][4][4];
#pragma unroll
    for (int i = 0; i < 4; i++)
#pragma unroll
        for (int j = 0; j < 4; j++)
#pragma unroll
            for (int k = 0; k < 4; k++) acc[i][j][k] = 0.0f;

    uint32_t aF[2][4][4];
    uint32_t bF[2][4];
    float f2a = 0.0f, f2b = 0.0f;
    float4 v0, v1, v2, v3;

    // ---------- prologue (stages kbeg, kbeg+1) ----------
    {
        const size_t k0 = (size_t)kbeg * BK;
#pragma unroll
        for (int i = 0; i < 8; i++) cp16(sAu + soA + i * 4096, gA + (size_t)(32 * i) * DDIM + k0);
        CP_COMMIT();
#pragma unroll
        for (int i = 0; i < 8; i++)
            cp16(sAu + A_STAGE_BYTES + soA + i * 4096, gA + (size_t)(32 * i) * DDIM + k0 + BK);
        CP_COMMIT();
        v0 = *(const float4*)(gB0 + k0);
        v1 = *(const float4*)(gB0 + k0 + 4);
        v2 = *(const float4*)(gB1 + k0);
        v3 = *(const float4*)(gB1 + k0 + 4);
        CP_WAIT1();
        f2a += v0.x*v0.x + v0.y*v0.y + v0.z*v0.z + v0.w*v0.w
             + v1.x*v1.x + v1.y*v1.y + v1.z*v1.z + v1.w*v1.w;
        f2b += v2.x*v2.x + v2.y*v2.y + v2.z*v2.z + v2.w*v2.w
             + v3.x*v3.x + v3.y*v3.y + v3.z*v3.z + v3.w*v3.w;
        __nv_bfloat162 p0 = __floats2bfloat162_rn(v0.x, v0.y);
        __nv_bfloat162 p1 = __floats2bfloat162_rn(v0.z, v0.w);
        __nv_bfloat162 p2 = __floats2bfloat162_rn(v1.x, v1.y);
        __nv_bfloat162 p3 = __floats2bfloat162_rn(v1.z, v1.w);
        sts128u(sBcu + dstB, *(uint32_t*)&p0, *(uint32_t*)&p1, *(uint32_t*)&p2, *(uint32_t*)&p3);
        p0 = __floats2bfloat162_rn(v2.x, v2.y);
        p1 = __floats2bfloat162_rn(v2.z, v2.w);
        p2 = __floats2bfloat162_rn(v3.x, v3.y);
        p3 = __floats2bfloat162_rn(v3.z, v3.w);
        sts128u(sBcu + dstB + 32 * 128, *(uint32_t*)&p0, *(uint32_t*)&p1, *(uint32_t*)&p2, *(uint32_t*)&p3);
        v0 = *(const float4*)(gB0 + k0 + BK);
        v1 = *(const float4*)(gB0 + k0 + BK + 4);
        v2 = *(const float4*)(gB1 + k0 + BK);
        v3 = *(const float4*)(gB1 + k0 + BK + 4);
    }
    __syncthreads();

    // ---------- mainloop (R9 ordering) ----------
    int stage = 0;
    for (int it = 0; it < nk; it++) {
        const uint32_t abase = sAu + (uint32_t)stage * A_STAGE_BYTES;
        const uint32_t bbase = sBcu + (uint32_t)(it & 1) * B_STAGE_BYTES;

        {
            const uint32_t ch = hi;
#pragma unroll
            for (int mt = 0; mt < 4; mt++)
                ldsm_x4(aF[0][mt], abase + (uint32_t)((rowA + mt * 16) * 128) + ((ch ^ xA) << 4));
        }

        if (it + 2 < nk) {
            const int s2 = (stage >= 1) ? stage - 1 : stage + 2;
            const size_t ko = (size_t)(kbeg + it + 2) * BK;
#pragma unroll
            for (int i = 0; i < 8; i++)
                cp16(sAu + (uint32_t)s2 * A_STAGE_BYTES + soA + i * 4096,
                     gA + (size_t)(32 * i) * DDIM + ko);
            CP_COMMIT();
        }

#pragma unroll
        for (int ks = 0; ks < 4; ks++) {
            const int cur = ks & 1;
            {
                const uint32_t ch = (uint32_t)(ks * 2) + hi;
                ldsm_x4(bF[0], bbase + (uint32_t)(rowB0 * 128) + ((ch ^ xB0) << 4));
                ldsm_x4(bF[1], bbase + (uint32_t)(rowB1 * 128) + ((ch ^ xB1) << 4));
            }
            if (ks < 3) {
                const uint32_t ch = (uint32_t)((ks + 1) * 2) + hi;
#pragma unroll
                for (int mt = 0; mt < 4; mt++)
                    ldsm_x4(aF[cur ^ 1][mt],
                            abase + (uint32_t)((rowA + mt * 16) * 128) + ((ch ^ xA) << 4));
            }
#pragma unroll
            for (int mt = 0; mt < 4; mt++)
#pragma unroll
                for (int nt = 0; nt < 4; nt++)
                    mma16816(acc[mt][nt], aF[cur][mt], bF[nt >> 1][nt & 1], bF[nt >> 1][2 + (nt & 1)]);
        }

        if (it + 1 < nk) {
            if (it + 2 < nk) { CP_WAIT1(); } else { CP_WAIT0(); }
            {
                f2a += v0.x*v0.x + v0.y*v0.y + v0.z*v0.z + v0.w*v0.w
                     + v1.x*v1.x + v1.y*v1.y + v1.z*v1.z + v1.w*v1.w;
                f2b += v2.x*v2.x + v2.y*v2.y + v2.z*v2.z + v2.w*v2.w
                     + v3.x*v3.x + v3.y*v3.y + v3.z*v3.z + v3.w*v3.w;
                const uint32_t bb = sBcu + (uint32_t)((it + 1) & 1) * B_STAGE_BYTES;
                __nv_bfloat162 p0 = __floats2bfloat162_rn(v0.x, v0.y);
                __nv_bfloat162 p1 = __floats2bfloat162_rn(v0.z, v0.w);
                __nv_bfloat162 p2 = __floats2bfloat162_rn(v1.x, v1.y);
                __nv_bfloat162 p3 = __floats2bfloat162_rn(v1.z, v1.w);
                sts128u(bb + dstB, *(uint32_t*)&p0, *(uint32_t*)&p1, *(uint32_t*)&p2, *(uint32_t*)&p3);
                p0 = __floats2bfloat162_rn(v2.x, v2.y);
                p1 = __floats2bfloat162_rn(v2.z, v2.w);
                p2 = __floats2bfloat162_rn(v3.x, v3.y);
                p3 = __floats2bfloat162_rn(v3.z, v3.w);
                sts128u(bb + dstB + 32 * 128, *(uint32_t*)&p0, *(uint32_t*)&p1, *(uint32_t*)&p2, *(uint32_t*)&p3);
            }
            if (it + 2 < nk) {
                const size_t ko = (size_t)(kbeg + it + 2) * BK;
                v0 = *(const float4*)(gB0 + ko);
                v1 = *(const float4*)(gB0 + ko + 4);
                v2 = *(const float4*)(gB1 + ko);
                v3 = *(const float4*)(gB1 + ko + 4);
            }
            __syncthreads();
        }
        stage = (stage >= 2) ? 0 : stage + 1;
    }

    // ---- f2 output ----
    f2a += __shfl_down_sync(0xffffffffu, f2a, 4, 8);
    f2a += __shfl_down_sync(0xffffffffu, f2a, 2, 8);
    f2a += __shfl_down_sync(0xffffffffu, f2a, 1, 8);
    f2b += __shfl_down_sync(0xffffffffu, f2b, 4, 8);
    f2b += __shfl_down_sync(0xffffffffu, f2b, 2, 8);
    f2b += __shfl_down_sync(0xffffffffu, f2b, 1, 8);
    if (bseg == 0) {
        if (part == 0) {
            g_f2[br * NF + n0 + brow] = f2a;
            g_f2[br * NF + n0 + brow + 32] = f2b;
        } else {
            g_f2x[(part - 1) * EXCOLS + (n0 - EXCOL0) + brow] = f2a;
            g_f2x[(part - 1) * EXCOLS + (n0 - EXCOL0) + brow + 32] = f2b;
        }
    }

    // ---- C output: bf16 for full tiles, fp32 for split partials ----
    const int rr = lid >> 2;
    const int cc = (lid & 3) * 2;
    if (part == 0) {
        __nv_bfloat16* Cb = g_dotb + (size_t)(br * BSZ + warp_m * 64) * NF + n0 + warp_n * 32;
#pragma unroll
        for (int mt = 0; mt < 4; mt++)
#pragma unroll
            for (int nt = 0; nt < 4; nt++) {
                __nv_bfloat162 h0 = __floats2bfloat162_rn(acc[mt][nt][0], acc[mt][nt][1]);
                __nv_bfloat162 h1 = __floats2bfloat162_rn(acc[mt][nt][2], acc[mt][nt][3]);
                *(__nv_bfloat162*)&Cb[(size_t)(mt * 16 + rr) * NF + nt * 8 + cc] = h0;
                *(__nv_bfloat162*)&Cb[(size_t)(mt * 16 + rr + 8) * NF + nt * 8 + cc] = h1;
            }
    } else {
        float* Cb = g_ex + ((size_t)(part - 1) * BSZ + warp_m * 64) * EXCOLS + (n0 - EXCOL0) + warp_n * 32;
#pragma unroll
        for (int mt = 0; mt < 4; mt++)
#pragma unroll
            for (int nt = 0; nt < 4; nt++) {
                float2 w0 = make_float2(acc[mt][nt][0], acc[mt][nt][1]);
                float2 w1 = make_float2(acc[mt][nt][2], acc[mt][nt][3]);
                *(float2*)&Cb[(size_t)(mt * 16 + rr) * EXCOLS + nt * 8 + cc] = w0;
                *(float2*)&Cb[(size_t)(mt * 16 + rr + 8) * EXCOLS + nt * 8 + cc] = w1;
            }
    }
}

// ======================= kernel 3: per-row loss + last-block final reduce ===========
__global__ void __launch_bounds__(256) rowloss_kernel(
    const int* __restrict__ targets, float* __restrict__ out,
    const float* __restrict__ f0, const float* __restrict__ f1, const float* __restrict__ f2in)
{
    const int r = blockIdx.x;
    const int br = r >> 8;
    const int b = r & 255;
    const __nv_bfloat16* drow = g_dotb + (size_t)r * NF;
    const float* f2 = g_f2 + br * NF;
    const float* ex0 = g_ex + (size_t)b * EXCOLS;
    const float* ex1 = g_ex + (size_t)(BSZ + b) * EXCOLS;
    const float x2 = g_x2[r];
    const int tid = threadIdx.x;
    const bool isSplitBr = (br == 2);
    const int t = targets[b];

    __shared__ float sm[NF];

    // exact target-dot recompute (mimics GEMM's bf16 rounding)
    const __nv_bfloat16* X = g_xn + (size_t)r * DDIM;
    const float* Ft = ((br == 0) ? f0 : (br == 1) ? f1 : f2in) + (size_t)t * DDIM;
    float dta = 0.0f;
#pragma unroll
    for (int i = 0; i < 8; i++) {
        const int idx = tid + i * 256;
        float fb = __bfloat162float(__float2bfloat16(Ft[idx]));
        dta += fb * __bfloat162float(X[idx]);
    }
    dta = blockReduceSum(dta);
    __shared__ float s_dott;
    if (tid == 0) s_dott = dta;

    float s1 = 0.0f, s2 = 0.0f;
#pragma unroll 4
    for (int i = 0; i < NF / 256; i++) {
        int n = tid + i * 256;
        float dot = __bfloat162float(drow[n]);
        float ff = f2[n];
        if (isSplitBr && n >= EXCOL0) {
            int e = n - EXCOL0;
            dot += ex0[e] + ex1[e];
            ff += g_f2x[e] + g_f2x[EXCOLS + e];
        }
        s1 += expf(dot * TEMP_INV);
        float d2 = x2 + ff - 2.0f * dot;
        float d = sqrtf(fmaxf(d2, 0.0f));
        float ed = expf(d);
        s2 += ed;
        sm[n] = ed;
    }
    s1 = blockReduceSum(s1);
    __shared__ float sS1;
    if (tid == 0) sS1 = s1;
    s2 = blockReduceSum(s2);
    __shared__ float sS2;
    if (tid == 0) sS2 = s2;
    __syncthreads();
    const float inv2 = 1.0f / sS2;

    float s3 = 0.0f;
#pragma unroll 4
    for (int i = 0; i < NF / 256; i++) {
        int n = tid + i * 256;
        s3 += expf(sm[n] * inv2);
    }
    s3 = blockReduceSum(s3);

    if (tid == 0) {
        const float dott = s_dott;
        float f2t = f2[t];
        if (isSplitBr && t >= EXCOL0) {
            int e = t - EXCOL0;
            f2t += g_f2x[e] + g_f2x[EXCOLS + e];
        }
        float d2t = x2 + f2t - 2.0f * dott;
        float dt = sqrtf(fmaxf(d2t, 0.0f));
        float loss1 = logf(sS1) - dott * TEMP_INV;
        float loss2 = logf(s3) - expf(dt) * inv2;
        g_rowloss[r] = loss1 + loss2;
    }

    __shared__ int s_isLast;
    __threadfence();
    if (tid == 0) {
        int c = atomicAdd(&g_count, 1);
        s_isLast = (c == NB * BSZ - 1) ? 1 : 0;
    }
    __syncthreads();
    if (s_isLast) {
        float v2 = g_rowloss[tid] + g_rowloss[tid + 256] + g_rowloss[tid + 512];
        v2 = blockReduceSum(v2);
        if (tid == 0) {
            out[0] = v2 * (0.5f / 256.0f);
            g_count = 0;
        }
    }
}

// ======================= launch =======================
extern "C" void kernel_launch(void* const* d_in, const int* in_sizes, int n_in,
                              void* d_out, int out_size) {
    const float* inputs      = (const float*)d_in[0];
    const float* inputs_up   = (const float*)d_in[1];
    const float* inputs_down = (const float*)d_in[2];
    const int*   targets     = (const int*)d_in[3];
    const float* features      = (const float*)d_in[5];
    const float* features_up   = (const float*)d_in[6];
    const float* features_down = (const float*)d_in[7];
    float* out = (float*)d_out;

    cudaFuncSetAttribute(gemm_fused_kernel,
                         cudaFuncAttributeMaxDynamicSharedMemorySize, SMEM_DYN);

    prep_x_kernel<<<NB * BSZ / 2, 256>>>(inputs, inputs_up, inputs_down);
    gemm_fused_kernel<<<NT_FULL + 88 * 3, 256, SMEM_DYN>>>(features, features_up, features_down);
    rowloss_kernel<<<NB * BSZ, 256>>>(targets, out, features, features_up, features_down);
}

// round 17
// speedup vs baseline: 1.0270x; 1.0270x over previous
#include <cuda_runtime.h>
#include <cuda_bf16.h>
#include <cstdint>

// ======================= problem constants =======================
#define NB   3
#define BSZ  256
#define NF   8192
#define DDIM 2048
#define TEMP_INV 20.0f
#define NEPS 1e-12f

// GEMM tiling (R9 config)
#define BM 256
#define BN 64
#define BK 64
#define NK (DDIM / BK)                 // 32
#define A_STAGE_BYTES (BM * BK * 2)    // 32768
#define B_STAGE_BYTES (BN * BK * 2)    // 8192
#define SMEM_DYN (3 * A_STAGE_BYTES + 2 * B_STAGE_BYTES)  // 114688

// tile schedule: 384 tiles; first 296 full-K, last 88 (br=2, ntile>=40) split 3-way.
#define NT_FULL 296
#define SPLIT_NT0 40
#define EXCOLS ((128 - SPLIT_NT0) * BN)  // 5632
#define EXCOL0 (SPLIT_NT0 * BN)          // 2560

// ======================= static device scratch =======================
__device__ __align__(256) __nv_bfloat16 g_xn[NB * BSZ * DDIM];
__device__ float g_x2[NB * BSZ];
__device__ float g_f2[NB * NF];
__device__ __align__(256) float g_dot[(size_t)NB * BSZ * NF];
__device__ __align__(256) float g_ex[(size_t)2 * BSZ * EXCOLS];
__device__ float g_f2x[2 * EXCOLS];
__device__ float g_rowloss[NB * BSZ];
__device__ int g_count;

// ======================= helpers =======================
__device__ __forceinline__ uint32_t smem_u32(const void* p) {
    uint32_t a;
    asm("{ .reg .u64 t; cvta.to.shared.u64 t, %1; cvt.u32.u64 %0, t; }" : "=r"(a) : "l"(p));
    return a;
}

__device__ __forceinline__ void cp16(uint32_t saddr, const void* g) {
    asm volatile("cp.async.cg.shared.global [%0], [%1], 16;" :: "r"(saddr), "l"(g) : "memory");
}
#define CP_COMMIT() asm volatile("cp.async.commit_group;" ::: "memory")
#define CP_WAIT0()  asm volatile("cp.async.wait_group 0;" ::: "memory")
#define CP_WAIT1()  asm volatile("cp.async.wait_group 1;" ::: "memory")

__device__ __forceinline__ void ldsm_x4(uint32_t* r, uint32_t addr) {
    asm volatile("ldmatrix.sync.aligned.m8n8.x4.shared.b16 {%0,%1,%2,%3}, [%4];"
                 : "=r"(r[0]), "=r"(r[1]), "=r"(r[2]), "=r"(r[3]) : "r"(addr));
}

__device__ __forceinline__ void mma16816(float* c, const uint32_t* a, uint32_t b0, uint32_t b1) {
    asm volatile(
        "mma.sync.aligned.m16n8k16.row.col.f32.bf16.bf16.f32 "
        "{%0,%1,%2,%3}, {%4,%5,%6,%7}, {%8,%9}, {%0,%1,%2,%3};"
        : "+f"(c[0]), "+f"(c[1]), "+f"(c[2]), "+f"(c[3])
        : "r"(a[0]), "r"(a[1]), "r"(a[2]), "r"(a[3]), "r"(b0), "r"(b1));
}

__device__ __forceinline__ void sts128u(uint32_t addr, uint32_t x, uint32_t y, uint32_t z, uint32_t w) {
    asm volatile("st.shared.v4.b32 [%0], {%1, %2, %3, %4};"
                 :: "r"(addr), "r"(x), "r"(y), "r"(z), "r"(w) : "memory");
}

__device__ __forceinline__ float blockReduceSum(float v) {
    __shared__ float red[8];
    const unsigned m = 0xffffffffu;
    v += __shfl_xor_sync(m, v, 16);
    v += __shfl_xor_sync(m, v, 8);
    v += __shfl_xor_sync(m, v, 4);
    v += __shfl_xor_sync(m, v, 2);
    v += __shfl_xor_sync(m, v, 1);
    __syncthreads();
    if ((threadIdx.x & 31) == 0) red[threadIdx.x >> 5] = v;
    __syncthreads();
    if (threadIdx.x < 8) {
        v = red[threadIdx.x];
        v += __shfl_xor_sync(0xffu, v, 4);
        v += __shfl_xor_sync(0xffu, v, 2);
        v += __shfl_xor_sync(0xffu, v, 1);
    }
    return v;
}

// ======================= kernel 1: normalize x rows -> bf16 (float4 path) ===========
__global__ void __launch_bounds__(256) prep_x_kernel(
    const float* __restrict__ x0, const float* __restrict__ x1, const float* __restrict__ x2)
{
    const int r = blockIdx.x;
    const int tid = threadIdx.x;
    const int br = r >> 8;
    const int b = r & 255;
    const float* base = (br == 0) ? x0 : (br == 1) ? x1 : x2;
    const float4* src = (const float4*)(base + (size_t)b * DDIM);
    __nv_bfloat162* dst = (__nv_bfloat162*)(g_xn + (size_t)r * DDIM);

    float4 v[2];
    float ss = 0.0f;
#pragma unroll
    for (int i = 0; i < 2; i++) {
        v[i] = src[tid + i * 256];
        ss += v[i].x * v[i].x + v[i].y * v[i].y + v[i].z * v[i].z + v[i].w * v[i].w;
    }
    ss = blockReduceSum(ss);
    __shared__ float s_bcast;
    if (tid == 0) s_bcast = ss;
    __syncthreads();
    ss = s_bcast;

    float nrm = sqrtf(ss);
    float scale = 1.0f / fmaxf(nrm, NEPS);
    if (tid == 0) g_x2[r] = ss * scale * scale;
#pragma unroll
    for (int i = 0; i < 2; i++) {
        dst[(tid + i * 256) * 2 + 0] = __floats2bfloat162_rn(v[i].x * scale, v[i].y * scale);
        dst[(tid + i * 256) * 2 + 1] = __floats2bfloat162_rn(v[i].z * scale, v[i].w * scale);
    }
}

// ======================= kernel 2: fused convert + GEMM + f2, asymmetric split-K ====
__global__ void __launch_bounds__(256, 2) gemm_fused_kernel(
    const float* __restrict__ f0, const float* __restrict__ f1, const float* __restrict__ f2in)
{
    extern __shared__ __align__(128) char dyn[];
    const uint32_t sAu  = smem_u32(dyn);                         // 3 x 32KB
    const uint32_t sBcu = sAu + 3 * A_STAGE_BYTES;               // 2 x 8KB

    const int tid = threadIdx.x;
    const int wid = tid >> 5;
    const int lid = tid & 31;

    // ---- tile decode: full tiles first in launch order, then split parts ----
    const int bid = blockIdx.x;
    int br, ntile, part, kbeg, nk;
    if (bid < NT_FULL) {
        br = bid >> 7; ntile = bid & 127; part = 0; kbeg = 0; nk = NK;
    } else {
        int u = bid - NT_FULL;
        int st = u / 3;
        part = u - st * 3;
        br = 2; ntile = SPLIT_NT0 + st;
        kbeg = (part == 0) ? 0 : ((part == 1) ? 11 : 22);
        nk = (part == 0) ? 11 : ((part == 1) ? 11 : 10);
    }
    const int n0 = ntile * BN;
    const int warp_m = wid & 3;
    const int warp_n = wid >> 2;

    const __nv_bfloat16* __restrict__ Ab = g_xn + (size_t)(br * BSZ) * DDIM;
    const float* __restrict__ Fb = ((br == 0) ? f0 : (br == 1) ? f1 : f2in) + (size_t)n0 * DDIM;

    // --- A cp.async mapping ---
    const int arow = tid >> 3;
    const int aseg = tid & 7;
    const uint32_t soA = (uint32_t)(arow * 128 + ((aseg ^ (arow & 7)) << 4));
    const __nv_bfloat16* gA = Ab + (size_t)arow * DDIM + aseg * 8;

    // --- B mapping ---
    const int brow = tid >> 3;
    const int bseg = tid & 7;
    const float* gB0 = Fb + (size_t)brow * DDIM + bseg * 8;
    const float* gB1 = gB0 + (size_t)32 * DDIM;
    const uint32_t dstB = (uint32_t)(brow * 128 + ((bseg ^ (brow & 7)) << 4));

    // --- ldmatrix fragment bases ---
    const int rowA = warp_m * 64 + (lid & 15);
    const uint32_t xA = (uint32_t)(rowA & 7);
    const int rowB0 = warp_n * 32 + (lid & 15);
    const int rowB1 = rowB0 + 16;
    const uint32_t xB0 = (uint32_t)(rowB0 & 7);
    const uint32_t xB1 = (uint32_t)(rowB1 & 7);
    const uint32_t hi = (uint32_t)(lid >> 4);

    float acc[4][4][4];
#pragma unroll
    for (int i = 0; i < 4; i++)
#pragma unroll
        for (int j = 0; j < 4; j++)
#pragma unroll
            for (int k = 0; k < 4; k++) acc[i][j][k] = 0.0f;

    uint32_t aF[2][4][4];
    uint32_t bF[2][4];
    float f2a = 0.0f, f2b = 0.0f;
    float4 v0, v1, v2, v3;

    // ---------- prologue (stages kbeg, kbeg+1) ----------
    {
        const size_t k0 = (size_t)kbeg * BK;
#pragma unroll
        for (int i = 0; i < 8; i++) cp16(sAu + soA + i * 4096, gA + (size_t)(32 * i) * DDIM + k0);
        CP_COMMIT();
#pragma unroll
        for (int i = 0; i < 8; i++)
            cp16(sAu + A_STAGE_BYTES + soA + i * 4096, gA + (size_t)(32 * i) * DDIM + k0 + BK);
        CP_COMMIT();
        v0 = *(const float4*)(gB0 + k0);
        v1 = *(const float4*)(gB0 + k0 + 4);
        v2 = *(const float4*)(gB1 + k0);
        v3 = *(const float4*)(gB1 + k0 + 4);
        CP_WAIT1();
        f2a += v0.x*v0.x + v0.y*v0.y + v0.z*v0.z + v0.w*v0.w
             + v1.x*v1.x + v1.y*v1.y + v1.z*v1.z + v1.w*v1.w;
        f2b += v2.x*v2.x + v2.y*v2.y + v2.z*v2.z + v2.w*v2.w
             + v3.x*v3.x + v3.y*v3.y + v3.z*v3.z + v3.w*v3.w;
        __nv_bfloat162 p0 = __floats2bfloat162_rn(v0.x, v0.y);
        __nv_bfloat162 p1 = __floats2bfloat162_rn(v0.z, v0.w);
        __nv_bfloat162 p2 = __floats2bfloat162_rn(v1.x, v1.y);
        __nv_bfloat162 p3 = __floats2bfloat162_rn(v1.z, v1.w);
        sts128u(sBcu + dstB, *(uint32_t*)&p0, *(uint32_t*)&p1, *(uint32_t*)&p2, *(uint32_t*)&p3);
        p0 = __floats2bfloat162_rn(v2.x, v2.y);
        p1 = __floats2bfloat162_rn(v2.z, v2.w);
        p2 = __floats2bfloat162_rn(v3.x, v3.y);
        p3 = __floats2bfloat162_rn(v3.z, v3.w);
        sts128u(sBcu + dstB + 32 * 128, *(uint32_t*)&p0, *(uint32_t*)&p1, *(uint32_t*)&p2, *(uint32_t*)&p3);
        v0 = *(const float4*)(gB0 + k0 + BK);
        v1 = *(const float4*)(gB0 + k0 + BK + 4);
        v2 = *(const float4*)(gB1 + k0 + BK);
        v3 = *(const float4*)(gB1 + k0 + BK + 4);
    }
    __syncthreads();

    // ---------- mainloop (R9 ordering) ----------
    int stage = 0;
    for (int it = 0; it < nk; it++) {
        const uint32_t abase = sAu + (uint32_t)stage * A_STAGE_BYTES;
        const uint32_t bbase = sBcu + (uint32_t)(it & 1) * B_STAGE_BYTES;

        {
            const uint32_t ch = hi;
#pragma unroll
            for (int mt = 0; mt < 4; mt++)
                ldsm_x4(aF[0][mt], abase + (uint32_t)((rowA + mt * 16) * 128) + ((ch ^ xA) << 4));
        }

        if (it + 2 < nk) {
            const int s2 = (stage >= 1) ? stage - 1 : stage + 2;
            const size_t ko = (size_t)(kbeg + it + 2) * BK;
#pragma unroll
            for (int i = 0; i < 8; i++)
                cp16(sAu + (uint32_t)s2 * A_STAGE_BYTES + soA + i * 4096,
                     gA + (size_t)(32 * i) * DDIM + ko);
            CP_COMMIT();
        }

#pragma unroll
        for (int ks = 0; ks < 4; ks++) {
            const int cur = ks & 1;
            {
                const uint32_t ch = (uint32_t)(ks * 2) + hi;
                ldsm_x4(bF[0], bbase + (uint32_t)(rowB0 * 128) + ((ch ^ xB0) << 4));
                ldsm_x4(bF[1], bbase + (uint32_t)(rowB1 * 128) + ((ch ^ xB1) << 4));
            }
            if (ks < 3) {
                const uint32_t ch = (uint32_t)((ks + 1) * 2) + hi;
#pragma unroll
                for (int mt = 0; mt < 4; mt++)
                    ldsm_x4(aF[cur ^ 1][mt],
                            abase + (uint32_t)((rowA + mt * 16) * 128) + ((ch ^ xA) << 4));
            }
#pragma unroll
            for (int mt = 0; mt < 4; mt++)
#pragma unroll
                for (int nt = 0; nt < 4; nt++)
                    mma16816(acc[mt][nt], aF[cur][mt], bF[nt >> 1][nt & 1], bF[nt >> 1][2 + (nt & 1)]);
        }

        if (it + 1 < nk) {
            if (it + 2 < nk) { CP_WAIT1(); } else { CP_WAIT0(); }
            {
                f2a += v0.x*v0.x + v0.y*v0.y + v0.z*v0.z + v0.w*v0.w
                     + v1.x*v1.x + v1.y*v1.y + v1.z*v1.z + v1.w*v1.w;
                f2b += v2.x*v2.x + v2.y*v2.y + v2.z*v2.z + v2.w*v2.w
                     + v3.x*v3.x + v3.y*v3.y + v3.z*v3.z + v3.w*v3.w;
                const uint32_t bb = sBcu + (uint32_t)((it + 1) & 1) * B_STAGE_BYTES;
                __nv_bfloat162 p0 = __floats2bfloat162_rn(v0.x, v0.y);
                __nv_bfloat162 p1 = __floats2bfloat162_rn(v0.z, v0.w);
                __nv_bfloat162 p2 = __floats2bfloat162_rn(v1.x, v1.y);
                __nv_bfloat162 p3 = __floats2bfloat162_rn(v1.z, v1.w);
                sts128u(bb + dstB, *(uint32_t*)&p0, *(uint32_t*)&p1, *(uint32_t*)&p2, *(uint32_t*)&p3);
                p0 = __floats2bfloat162_rn(v2.x, v2.y);
                p1 = __floats2bfloat162_rn(v2.z, v2.w);
                p2 = __floats2bfloat162_rn(v3.x, v3.y);
                p3 = __floats2bfloat162_rn(v3.z, v3.w);
                sts128u(bb + dstB + 32 * 128, *(uint32_t*)&p0, *(uint32_t*)&p1, *(uint32_t*)&p2, *(uint32_t*)&p3);
            }
            if (it + 2 < nk) {
                const size_t ko = (size_t)(kbeg + it + 2) * BK;
                v0 = *(const float4*)(gB0 + ko);
                v1 = *(const float4*)(gB0 + ko + 4);
                v2 = *(const float4*)(gB1 + ko);
                v3 = *(const float4*)(gB1 + ko + 4);
            }
            __syncthreads();
        }
        stage = (stage >= 2) ? 0 : stage + 1;
    }

    // ---- f2 output ----
    f2a += __shfl_down_sync(0xffffffffu, f2a, 4, 8);
    f2a += __shfl_down_sync(0xffffffffu, f2a, 2, 8);
    f2a += __shfl_down_sync(0xffffffffu, f2a, 1, 8);
    f2b += __shfl_down_sync(0xffffffffu, f2b, 4, 8);
    f2b += __shfl_down_sync(0xffffffffu, f2b, 2, 8);
    f2b += __shfl_down_sync(0xffffffffu, f2b, 1, 8);
    if (bseg == 0) {
        if (part == 0) {
            g_f2[br * NF + n0 + brow] = f2a;
            g_f2[br * NF + n0 + brow + 32] = f2b;
        } else {
            g_f2x[(part - 1) * EXCOLS + (n0 - EXCOL0) + brow] = f2a;
            g_f2x[(part - 1) * EXCOLS + (n0 - EXCOL0) + brow + 32] = f2b;
        }
    }

    // ---- C output ----
    float* Cbase;
    size_t cst;
    if (part == 0) {
        Cbase = g_dot + (size_t)(br * BSZ + warp_m * 64) * NF + n0 + warp_n * 32;
        cst = NF;
    } else {
        Cbase = g_ex + ((size_t)(part - 1) * BSZ + warp_m * 64) * EXCOLS + (n0 - EXCOL0) + warp_n * 32;
        cst = EXCOLS;
    }
    const int rr = lid >> 2;
    const int cc = (lid & 3) * 2;
#pragma unroll
    for (int mt = 0; mt < 4; mt++)
#pragma unroll
        for (int nt = 0; nt < 4; nt++) {
            float2 w0 = make_float2(acc[mt][nt][0], acc[mt][nt][1]);
            float2 w1 = make_float2(acc[mt][nt][2], acc[mt][nt][3]);
            *(float2*)&Cbase[(size_t)(mt * 16 + rr) * cst + nt * 8 + cc] = w0;
            *(float2*)&Cbase[(size_t)(mt * 16 + rr + 8) * cst + nt * 8 + cc] = w1;
        }
}

// ======================= kernel 3: single-pass per-row loss + final reduce ===========
// Pass 2 (exp of softmax values) replaced by Taylor expansion:
//   sum_n exp(u_n) = NF + 1 + E2/(2 S2^2) + E3/(6 S2^3) + O(sum u^4/24),  u_n = e^{d_n}/S2
// (validated in R5: same formula gave rel_err 9.8e-7)
__global__ void __launch_bounds__(256) rowloss_kernel(const int* __restrict__ targets,
                                                      float* __restrict__ out) {
    const int r = blockIdx.x;
    const int br = r >> 8;
    const int b = r & 255;
    const float* drow = g_dot + (size_t)r * NF;
    const float* f2 = g_f2 + br * NF;
    const float* ex0 = g_ex + (size_t)b * EXCOLS;
    const float* ex1 = g_ex + (size_t)(BSZ + b) * EXCOLS;
    const float x2 = g_x2[r];
    const int tid = threadIdx.x;
    const bool isSplitBr = (br == 2);

    float s1 = 0.0f, t1 = 0.0f, t2 = 0.0f, t3 = 0.0f;
#pragma unroll 4
    for (int i = 0; i < NF / 256; i++) {
        int n = tid + i * 256;
        float dot = drow[n];
        float ff = f2[n];
        if (isSplitBr && n >= EXCOL0) {
            int e = n - EXCOL0;
            dot += ex0[e] + ex1[e];
            ff += g_f2x[e] + g_f2x[EXCOLS + e];
        }
        s1 += expf(dot * TEMP_INV);
        float d2 = x2 + ff - 2.0f * dot;
        float d = sqrtf(fmaxf(d2, 0.0f));
        float ed = expf(d);
        t1 += ed;
        t2 += ed * ed;
        t3 += ed * ed * ed;
    }
    s1 = blockReduceSum(s1);
    __shared__ float sS1;
    if (tid == 0) sS1 = s1;
    t1 = blockReduceSum(t1);
    __shared__ float sT1;
    if (tid == 0) sT1 = t1;
    t2 = blockReduceSum(t2);
    __shared__ float sT2;
    if (tid == 0) sT2 = t2;
    t3 = blockReduceSum(t3);

    if (tid == 0) {
        int t = targets[b];
        float dott = drow[t];
        float f2t = f2[t];
        if (isSplitBr && t >= EXCOL0) {
            int e = t - EXCOL0;
            dott += ex0[e] + ex1[e];
            f2t += g_f2x[e] + g_f2x[EXCOLS + e];
        }
        float d2t = x2 + f2t - 2.0f * dott;
        float dt = sqrtf(fmaxf(d2t, 0.0f));
        const float S2 = sT1;
        const float invS2 = 1.0f / S2;
        const float s3 = (float)NF + 1.0f
                       + 0.5f * sT2 * invS2 * invS2
                       + (1.0f / 6.0f) * t3 * invS2 * invS2 * invS2;
        float loss1 = logf(sS1) - dott * TEMP_INV;
        float loss2 = logf(s3) - expf(dt) * invS2;
        g_rowloss[r] = loss1 + loss2;
    }

    __shared__ int s_isLast;
    __threadfence();
    if (tid == 0) {
        int c = atomicAdd(&g_count, 1);
        s_isLast = (c == NB * BSZ - 1) ? 1 : 0;
    }
    __syncthreads();
    if (s_isLast) {
        float v2 = g_rowloss[tid] + g_rowloss[tid + 256] + g_rowloss[tid + 512];
        v2 = blockReduceSum(v2);
        if (tid == 0) {
            out[0] = v2 * (0.5f / 256.0f);
            g_count = 0;
        }
    }
}

// ======================= launch =======================
extern "C" void kernel_launch(void* const* d_in, const int* in_sizes, int n_in,
                              void* d_out, int out_size) {
    const float* inputs      = (const float*)d_in[0];
    const float* inputs_up   = (const float*)d_in[1];
    const float* inputs_down = (const float*)d_in[2];
    const int*   targets     = (const int*)d_in[3];
    const float* features      = (const float*)d_in[5];
    const float* features_up   = (const float*)d_in[6];
    const float* features_down = (const float*)d_in[7];
    float* out = (float*)d_out;

    cudaFuncSetAttribute(gemm_fused_kernel,
                         cudaFuncAttributeMaxDynamicSharedMemorySize, SMEM_DYN);

    prep_x_kernel<<<NB * BSZ, 256>>>(inputs, inputs_up, inputs_down);
    gemm_fused_kernel<<<NT_FULL + 88 * 3, 256, SMEM_DYN>>>(features, features_up, features_down);
    rowloss_kernel<<<NB * BSZ, 256>>>(targets, out);
}